// round 16
// baseline (speedup 1.0000x reference)
#include <cuda_runtime.h>
#include <cuda_bf16.h>
#include <math.h>
#include <stdint.h>

#define BB 64
#define TT 256
#define HH 1024
#define VV 128
#define NG 4096   // 4*H

// ---------------- device scratch (no allocations allowed) ----------------
__device__ float g_gx[BB * TT * NG];              // gate pre-activations, T-major [T][B][4H]
__device__ __nv_bfloat16 g_y0b[BB * TT * HH];     // layer-0 output big
__device__ __nv_bfloat16 g_y0s[BB * TT * HH];     // layer-0 output small
__device__ __nv_bfloat16 g_y1b[BB * TT * HH];     // layer-1 output big
__device__ __nv_bfloat16 g_y1s[BB * TT * HH];     // layer-1 output small
__device__ __nv_bfloat16 g_hsb[2][BB * HH];       // hidden state big, double-buffered
__device__ __nv_bfloat16 g_hss[2][BB * HH];       // hidden state small, double-buffered
__device__ float g_c[BB * HH];                    // cell state (CTA-private cells)
__device__ float g_part[2][8 * BB * NG];          // k-split partials, double-buffered
__device__ __nv_bfloat16 g_wAb[NG * HH];          // W_ih / fc_W big
__device__ __nv_bfloat16 g_wAs[NG * HH];          // W_ih / fc_W small
__device__ __nv_bfloat16 g_embb[VV * HH];         // embedding big
__device__ __nv_bfloat16 g_embs[VV * HH];         // embedding small
__device__ unsigned g_barc;                       // global barrier arrival counter (init only)
__device__ volatile unsigned g_barsf[16 * 8];     // 16 release flags, 32B-spaced
__device__ volatile unsigned g_cnt2[8 * 8];       // per-ks-group h-ready counters (monotonic)
__device__ volatile unsigned g_cntcs[16 * 8];     // per-col-tile partials-ready counters (monotonic)

// ---------------- helpers ----------------
__device__ __forceinline__ void bf16_split(float x, __nv_bfloat16& b, __nv_bfloat16& s) {
    b = __float2bfloat16(x);
    s = __float2bfloat16(x - __bfloat162float(b));
}

__device__ __forceinline__ uint32_t pack_bf2(__nv_bfloat16 lo, __nv_bfloat16 hi) {
    __nv_bfloat162 t = __halves2bfloat162(lo, hi);
    return *reinterpret_cast<uint32_t*>(&t);
}

__device__ __forceinline__ int swz(int k2) {     // lstm custom swizzle (k2 mod 8)
    return 8 * (k2 & 3) + 16 * ((k2 >> 2) & 1);
}

__device__ __forceinline__ uint32_t sw64(uint32_t x) {   // SW64 (sgemm)
    return x ^ ((x >> 3) & 0x30);
}

__device__ __forceinline__ uint32_t smem_u32(const void* p) {
    uint32_t a;
    asm("{ .reg .u64 t; cvta.to.shared.u64 t, %1; cvt.u32.u64 %0, t; }" : "=r"(a) : "l"(p));
    return a;
}

__device__ __forceinline__ void mma_bf16(float* d, const uint32_t* a, const uint32_t* b) {
    asm volatile(
        "mma.sync.aligned.m16n8k16.row.col.f32.bf16.bf16.f32 "
        "{%0,%1,%2,%3}, {%4,%5,%6,%7}, {%8,%9}, {%0,%1,%2,%3};\n"
        : "+f"(d[0]), "+f"(d[1]), "+f"(d[2]), "+f"(d[3])
        : "r"(a[0]), "r"(a[1]), "r"(a[2]), "r"(a[3]), "r"(b[0]), "r"(b[1]));
}

__device__ __forceinline__ void ldsm4(uint32_t* r, uint32_t addr) {
    asm volatile(
        "ldmatrix.sync.aligned.m8n8.x4.shared.b16 {%0,%1,%2,%3}, [%4];"
        : "=r"(r[0]), "=r"(r[1]), "=r"(r[2]), "=r"(r[3]) : "r"(addr));
}

__device__ __forceinline__ float rcp_approx(float d) {
    float r;
    asm("rcp.approx.f32 %0, %1;" : "=f"(r) : "f"(d));
    return r;
}

__device__ __forceinline__ float fast_sigmoid(float x) {   // 1/(1+e^-x)
    const float a = fmaxf(fminf(-x, 40.f), -40.f);
    return rcp_approx(1.f + __expf(a));
}

__device__ __forceinline__ float fast_tanh(float x) {      // 1 - 2/(e^{2x}+1)
    const float a = fmaxf(fminf(2.f * x, 40.f), -40.f);
    return 1.f - 2.f * rcp_approx(__expf(a) + 1.f);
}

// Fused 3-product 16-k chunk, warp tile 64 x 16 (nf = 2):
// acc += Ab*Bb + Ab*Bs + As*Bb.  Scalar-LDS fragment path (proven fastest).
__device__ __forceinline__ void mma_chunk3_n2(const uint32_t* Ab32, const uint32_t* As32,
                                              const uint32_t* Bb32, const uint32_t* Bs32,
                                              int k2b, float acc[4][2][4],
                                              int nbase, int r, int q)
{
    const int s0 = 8 * r;
    const int s1 = 8 * r + 16;
    const int ra0 = (k2b + r) * 64;
    const int ra1 = (k2b + r + 4) * 64;
    const int rb0 = (k2b + r) * 256;
    const int rb1 = (k2b + r + 4) * 256;
    uint32_t bb[2][2], bs[2][2];
    #pragma unroll
    for (int nf = 0; nf < 2; nf++) {
        const int cb = nbase + nf * 8 + q;
        bb[nf][0] = Bb32[rb0 + (cb ^ s0)];
        bb[nf][1] = Bb32[rb1 + (cb ^ s1)];
        bs[nf][0] = Bs32[rb0 + (cb ^ s0)];
        bs[nf][1] = Bs32[rb1 + (cb ^ s1)];
    }
    {
        uint32_t ab[4][4];
        #pragma unroll
        for (int mf = 0; mf < 4; mf++) {
            const int c0 = mf * 16 + q;
            ab[mf][0] = Ab32[ra0 + (c0 ^ s0)];
            ab[mf][1] = Ab32[ra0 + ((c0 + 8) ^ s0)];
            ab[mf][2] = Ab32[ra1 + (c0 ^ s1)];
            ab[mf][3] = Ab32[ra1 + ((c0 + 8) ^ s1)];
        }
        #pragma unroll
        for (int mf = 0; mf < 4; mf++)
            #pragma unroll
            for (int nf = 0; nf < 2; nf++)
                mma_bf16(acc[mf][nf], ab[mf], bb[nf]);
        #pragma unroll
        for (int mf = 0; mf < 4; mf++)
            #pragma unroll
            for (int nf = 0; nf < 2; nf++)
                mma_bf16(acc[mf][nf], ab[mf], bs[nf]);
    }
    {
        uint32_t as[4][4];
        #pragma unroll
        for (int mf = 0; mf < 4; mf++) {
            const int c0 = mf * 16 + q;
            as[mf][0] = As32[ra0 + (c0 ^ s0)];
            as[mf][1] = As32[ra0 + ((c0 + 8) ^ s0)];
            as[mf][2] = As32[ra1 + (c0 ^ s1)];
            as[mf][3] = As32[ra1 + ((c0 + 8) ^ s1)];
        }
        #pragma unroll
        for (int mf = 0; mf < 4; mf++)
            #pragma unroll
            for (int nf = 0; nf < 2; nf++)
                mma_bf16(acc[mf][nf], as[mf], bb[nf]);
    }
}

// ---------------- global barrier (init only) ----------------
__device__ __forceinline__ void grid_bar(unsigned* sense) {
    __syncthreads();
    if (threadIdx.x == 0) {
        unsigned s = *sense ^ 1u;
        *sense = s;
        __threadfence();                       // release
        unsigned prev = atomicAdd(&g_barc, 1u);
        if (prev == gridDim.x - 1) {
            g_barc = 0u;
            __threadfence();
            #pragma unroll
            for (int i = 0; i < 16; i++) g_barsf[i * 8] = s;
        } else {
            volatile unsigned* f = &g_barsf[(blockIdx.x >> 3) * 8];
            while (*f != s) { }
            __threadfence();                   // acquire
        }
    }
    __syncthreads();
}

// ---------------- fp32 -> (bf16 big, bf16 small) split ----------------
__global__ void cvt_split_kernel(const float* __restrict__ src,
                                 __nv_bfloat16* __restrict__ dstb,
                                 __nv_bfloat16* __restrict__ dsts, int n) {
    for (int i = blockIdx.x * blockDim.x + threadIdx.x; i < n; i += gridDim.x * blockDim.x) {
        __nv_bfloat16 b, s;
        bf16_split(src[i], b, s);
        dstb[i] = b;
        dsts[i] = s;
    }
}

// ---------------- ldmatrix split-bf16 SGEMM (unchanged from R13) ----------------
template <bool GATHER, bool TMAJOR>
__global__ __launch_bounds__(256, 2)
void sgemm_ldsm(const __nv_bfloat16* __restrict__ Ab, const __nv_bfloat16* __restrict__ As_,
                const int* __restrict__ tok,
                const __nv_bfloat16* __restrict__ Wb, const __nv_bfloat16* __restrict__ Ws_,
                const float* __restrict__ bias,
                float* __restrict__ C, int M, int N, int K)
{
    extern __shared__ uint8_t smg_raw[];
    uint8_t* smg = (uint8_t*)(((uintptr_t)smg_raw + 127) & ~(uintptr_t)127);
    const uint32_t smb = smem_u32(smg);

    const int tid = threadIdx.x;
    const int warp = tid >> 5;
    const int lane = tid & 31;
    const int m0 = blockIdx.y * 128;
    const int n0 = blockIdx.x * 128;
    const int mbase = (warp >> 2) * 64;
    const int nbase = (warp & 3) * 32;
    const int r = lane & 3;
    const int q = lane >> 2;

    uint32_t offA[4], offB[2];
    {
        const int ar = (lane & 7) + 8 * ((lane >> 3) & 1);
        const int abyt = ((lane >> 4) & 1) * 16;
        #pragma unroll
        for (int mf = 0; mf < 4; mf++)
            offA[mf] = sw64((mbase + mf * 16 + ar) * 64 + abyt);
        const int br = (lane & 7) + 8 * ((lane >> 4) & 1);
        const int bbyt = ((lane >> 3) & 1) * 16;
        #pragma unroll
        for (int n2 = 0; n2 < 2; n2++)
            offB[n2] = sw64((nbase + n2 * 16 + br) * 64 + bbyt);
    }

    const int srow = tid >> 1;
    const int so0i = srow * 64 + (tid & 1) * 32;
    const uint32_t so0 = sw64(so0i);
    const uint32_t so1 = sw64(so0i + 16);

    size_t aoff;
    if (GATHER) aoff = (size_t)tok[m0 + srow] * K;
    else        aoff = (size_t)(m0 + srow) * K;
    const __nv_bfloat16* arb = Ab  + aoff + (tid & 1) * 16;
    const __nv_bfloat16* ars = As_ + aoff + (tid & 1) * 16;
    const __nv_bfloat16* wrb = Wb  + (size_t)(n0 + srow) * K + (tid & 1) * 16;
    const __nv_bfloat16* wrs = Ws_ + (size_t)(n0 + srow) * K + (tid & 1) * 16;

    float acc[4][4][4];
    #pragma unroll
    for (int mf = 0; mf < 4; mf++)
        #pragma unroll
        for (int nf = 0; nf < 4; nf++)
            #pragma unroll
            for (int i = 0; i < 4; i++) acc[mf][nf][i] = 0.f;

    uint4 pab0 = *(const uint4*)(arb);
    uint4 pab1 = *(const uint4*)(arb + 8);
    uint4 pas0 = *(const uint4*)(ars);
    uint4 pas1 = *(const uint4*)(ars + 8);
    uint4 pwb0 = *(const uint4*)(wrb);
    uint4 pwb1 = *(const uint4*)(wrb + 8);
    uint4 pws0 = *(const uint4*)(wrs);
    uint4 pws1 = *(const uint4*)(wrs + 8);

    const int nslice = K / 32;
    for (int s = 0; s < nslice; s++) {
        const uint32_t bo = (uint32_t)(s & 1) * 32768u;
        *(uint4*)(smg + bo + so0)         = pab0;
        *(uint4*)(smg + bo + so1)         = pab1;
        *(uint4*)(smg + bo + 8192 + so0)  = pas0;
        *(uint4*)(smg + bo + 8192 + so1)  = pas1;
        *(uint4*)(smg + bo + 16384 + so0) = pwb0;
        *(uint4*)(smg + bo + 16384 + so1) = pwb1;
        *(uint4*)(smg + bo + 24576 + so0) = pws0;
        *(uint4*)(smg + bo + 24576 + so1) = pws1;
        if (s + 1 < nslice) {
            const int k0 = (s + 1) * 32;
            pab0 = *(const uint4*)(arb + k0);
            pab1 = *(const uint4*)(arb + k0 + 8);
            pas0 = *(const uint4*)(ars + k0);
            pas1 = *(const uint4*)(ars + k0 + 8);
            pwb0 = *(const uint4*)(wrb + k0);
            pwb1 = *(const uint4*)(wrb + k0 + 8);
            pws0 = *(const uint4*)(wrs + k0);
            pws1 = *(const uint4*)(wrs + k0 + 8);
        }
        __syncthreads();

        const uint32_t bAb = smb + bo;
        const uint32_t bAs = bAb + 8192;
        const uint32_t bBb = bAb + 16384;
        const uint32_t bBs = bAb + 24576;
        #pragma unroll
        for (int kc = 0; kc < 2; kc++) {
            const uint32_t kcb = (uint32_t)kc * 32u;
            uint32_t abf[4][4], bbf[2][4];
            #pragma unroll
            for (int mf = 0; mf < 4; mf++) ldsm4(abf[mf], bAb + (offA[mf] ^ kcb));
            #pragma unroll
            for (int n2 = 0; n2 < 2; n2++) ldsm4(bbf[n2], bBb + (offB[n2] ^ kcb));
            #pragma unroll
            for (int mf = 0; mf < 4; mf++)
                #pragma unroll
                for (int nf = 0; nf < 4; nf++)
                    mma_bf16(acc[mf][nf], abf[mf], &bbf[nf >> 1][(nf & 1) * 2]);
            {
                uint32_t bsf[2][4];
                #pragma unroll
                for (int n2 = 0; n2 < 2; n2++) ldsm4(bsf[n2], bBs + (offB[n2] ^ kcb));
                #pragma unroll
                for (int mf = 0; mf < 4; mf++)
                    #pragma unroll
                    for (int nf = 0; nf < 4; nf++)
                        mma_bf16(acc[mf][nf], abf[mf], &bsf[nf >> 1][(nf & 1) * 2]);
            }
            {
                uint32_t asf[4][4];
                #pragma unroll
                for (int mf = 0; mf < 4; mf++) ldsm4(asf[mf], bAs + (offA[mf] ^ kcb));
                #pragma unroll
                for (int mf = 0; mf < 4; mf++)
                    #pragma unroll
                    for (int nf = 0; nf < 4; nf++)
                        mma_bf16(acc[mf][nf], asf[mf], &bbf[nf >> 1][(nf & 1) * 2]);
            }
        }
    }

    #pragma unroll
    for (int nf = 0; nf < 4; nf++) {
        const int n = n0 + nbase + nf * 8 + 2 * r;
        const float b0v = bias[n];
        const float b1v = bias[n + 1];
        #pragma unroll
        for (int mf = 0; mf < 4; mf++) {
            const int m = m0 + mbase + mf * 16 + q;
            size_t row0, row1;
            if (TMAJOR) {
                row0 = (size_t)((m % TT) * BB + m / TT);
                const int m8 = m + 8;
                row1 = (size_t)((m8 % TT) * BB + m8 / TT);
            } else {
                row0 = (size_t)m;
                row1 = (size_t)(m + 8);
            }
            float2 o0 = {acc[mf][nf][0] + b0v, acc[mf][nf][1] + b1v};
            float2 o1 = {acc[mf][nf][2] + b0v, acc[mf][nf][3] + b1v};
            *(float2*)(C + row0 * N + n) = o0;
            *(float2*)(C + row1 * N + n) = o1;
        }
    }
}

// ---------------- persistent LSTM layer kernel: 512 threads (16 warps) ----------------
// grid = 128 CTAs (16 col tiles x 8 k-splits). W stationary (128 KB) + h tiles (32 KB)
// in 160 KB dyn smem. Warp tile 64x16 (nf=2). Scalar-LDS fragments.
// h pre-split in global (bf16 big/small) -> staging is pure 32-B copies per thread.
// Dependency-scoped sync identical to R12/R13.
__global__ __launch_bounds__(512, 1)
void lstm_layer(const float* __restrict__ gx, const float* __restrict__ Whh,
                const float* __restrict__ h0, const float* __restrict__ c0,
                __nv_bfloat16* __restrict__ yb, __nv_bfloat16* __restrict__ ys)
{
    extern __shared__ uint32_t dynsm[];
    uint32_t* Wb_sm = dynsm;               // [64 k2][256]  64 KB
    uint32_t* Ws_sm = dynsm + 64 * 256;    // 64 KB
    uint32_t* hb_sm = dynsm + 2 * 64 * 256;        // [64 k2][64]  16 KB
    uint32_t* hs_sm = dynsm + 2 * 64 * 256 + 64 * 64;

    const int tid = threadIdx.x;           // 0..511
    const int bid = blockIdx.x;            // 0..127
    const int cs  = bid & 15;
    const int ks  = bid >> 4;
    const int col0 = cs * 256;
    const int gtid = bid * 512 + tid;

    const int warp = tid >> 5;              // 0..15
    const int lane = tid & 31;
    const int r = lane & 3;
    const int q = lane >> 2;
    const int nbase = warp * 16;             // warp tile 64x16

    unsigned sense = g_barsf[(bid >> 3) * 8];

    // ---- one-time W slice load + split (2 threads per column) ----
    {
        const int wcol = tid >> 1;           // 0..255
        const int kh = (tid & 1) * 64;       // k half
        const float* wsrc = Whh + (size_t)(col0 + wcol) * HH + ks * 128 + kh;
        #pragma unroll
        for (int g = 0; g < 8; g++) {        // 8 k per iteration
            float4 v0 = *(const float4*)(wsrc + 8 * g);
            float4 v1 = *(const float4*)(wsrc + 8 * g + 4);
            const float wv[8] = {v0.x, v0.y, v0.z, v0.w, v1.x, v1.y, v1.z, v1.w};
            #pragma unroll
            for (int j = 0; j < 4; j++) {
                __nv_bfloat16 b0, s0, b1, s1;
                bf16_split(wv[2 * j], b0, s0);
                bf16_split(wv[2 * j + 1], b1, s1);
                const int k2 = (kh >> 1) + g * 4 + j;
                const int idx = k2 * 256 + (wcol ^ swz(k2));
                Wb_sm[idx] = pack_bf2(b0, b1);
                Ws_sm[idx] = pack_bf2(s0, s1);
            }
        }
    }

    // init: split h0, copy c, reset counters
    for (int i = gtid; i < BB * HH; i += 128 * 512) {
        __nv_bfloat16 b, s;
        bf16_split(h0[i], b, s);
        g_hsb[0][i] = b;
        g_hss[0][i] = s;
        g_c[i] = c0[i];
    }
    if (tid == 0 && bid < 8)  *((volatile unsigned*)&g_cnt2[bid * 8])  = 0u;
    if (tid == 0 && bid < 16) *((volatile unsigned*)&g_cntcs[bid * 8]) = 0u;
    grid_bar(&sense);

    // h staging: row = tid>>3 (0..63), 32-B k group = tid&7 (16 k = 8 k2 each)
    // coverage: 512 threads x 32 B = 16 KB = full 64x128 slice   (R15 bug fixed)
    const int hrow = tid >> 3;
    const int hkg  = tid & 7;
    const size_t hgoff = (size_t)hrow * HH + ks * 128 + hkg * 16;
    int hidx[8];
    #pragma unroll
    for (int j = 0; j < 8; j++) {
        const int k2 = hkg * 8 + j;
        hidx[j] = k2 * 64 + (hrow ^ swz(k2));
    }

    // phase-B ownership: 1 cell/thread; b in [4cs,4cs+4), j in [128ks,128ks+128)
    const int pb_b = 4 * cs + (tid >> 7);
    const int pb_j = 128 * ks + (tid & 127);
    const int cellp = pb_b * 1024 + pb_j;
    const int src_tile0 = ks >> 1;

    for (int t = 0; t < TT; t++) {
        const int par = t & 1;
        float* partp = g_part[par];

        // ---- group wait: own ks-group's h for this step ready ----
        if (t > 0) {
            if (tid == 0) {
                const unsigned need = 16u * (unsigned)t;
                volatile unsigned* cp = &g_cnt2[ks * 8];
                while (*cp < need) { }
                __threadfence();               // acquire
            }
            __syncthreads();
        }

        // ---- stage h: pure 2x16-B copies (no conversions), one sync ----
        {
            uint4 vb0 = *(const uint4*)(g_hsb[par] + hgoff);
            uint4 vb1 = *(const uint4*)(g_hsb[par] + hgoff + 8);
            uint4 vs0 = *(const uint4*)(g_hss[par] + hgoff);
            uint4 vs1 = *(const uint4*)(g_hss[par] + hgoff + 8);
            const uint32_t wb[8] = {vb0.x, vb0.y, vb0.z, vb0.w, vb1.x, vb1.y, vb1.z, vb1.w};
            const uint32_t ws[8] = {vs0.x, vs0.y, vs0.z, vs0.w, vs1.x, vs1.y, vs1.z, vs1.w};
            #pragma unroll
            for (int j = 0; j < 8; j++) {
                hb_sm[hidx[j]] = wb[j];
                hs_sm[hidx[j]] = ws[j];
            }
        }
        __syncthreads();

        float acc[4][2][4];
        #pragma unroll
        for (int mf = 0; mf < 4; mf++)
            #pragma unroll
            for (int nf = 0; nf < 2; nf++)
                #pragma unroll
                for (int i = 0; i < 4; i++) acc[mf][nf][i] = 0.f;

        #pragma unroll
        for (int kc = 0; kc < 8; kc++)
            mma_chunk3_n2(hb_sm, hs_sm, Wb_sm, Ws_sm, kc * 8, acc, nbase, r, q);

        // write partials P[par][ks][b][col]
        #pragma unroll
        for (int nf = 0; nf < 2; nf++) {
            const int col = col0 + nbase + nf * 8 + 2 * r;
            #pragma unroll
            for (int mf = 0; mf < 4; mf++) {
                const int b = mf * 16 + q;
                float2 o0 = {acc[mf][nf][0], acc[mf][nf][1]};
                float2 o1 = {acc[mf][nf][2], acc[mf][nf][3]};
                *(float2*)(&partp[((size_t)ks * BB + b) * NG + col])     = o0;
                *(float2*)(&partp[((size_t)ks * BB + b + 8) * NG + col]) = o1;
            }
        }

        // ---- prefetch gx[t] and c ----
        const float* gr = gx + (size_t)t * BB * NG + (size_t)pb_b * NG + pb_j;
        const float xg0 = gr[0];
        const float xg1 = gr[1024];
        const float xg2 = gr[2048];
        const float xg3 = gr[3072];
        float cv = g_c[cellp];

        // ---- signal own partials for step t ----
        __syncthreads();
        if (tid == 0) {
            __threadfence();                   // release partial writes
            atomicAdd((unsigned*)&g_cntcs[cs * 8], 1u);
        }

        // ---- wait: 4 source col tiles' partials ready ----
        if (tid < 4) {
            const unsigned need = 8u * (unsigned)(t + 1);
            volatile unsigned* cp = &g_cntcs[(src_tile0 + 4 * tid) * 8];
            while (*cp < need) { }
            __threadfence();                   // acquire
        }
        __syncthreads();

        // ---- Phase B: one cell per thread ----
        {
            float gi = xg0, gf = xg1, gg = xg2, go = xg3;
            #pragma unroll
            for (int s = 0; s < 8; s++) {
                const float* pp = &partp[((size_t)s * BB + pb_b) * NG + pb_j];
                gi += pp[0];
                gf += pp[1024];
                gg += pp[2048];
                go += pp[3072];
            }

            const float si = fast_sigmoid(gi);
            const float sf = fast_sigmoid(gf);
            const float so = fast_sigmoid(go);
            cv = sf * cv + si * fast_tanh(gg);
            const float hv = so * fast_tanh(cv);
            g_c[cellp] = cv;

            __nv_bfloat16 hb, hs;
            bf16_split(hv, hb, hs);
            g_hsb[par ^ 1][cellp] = hb;
            g_hss[par ^ 1][cellp] = hs;
            const size_t yi = ((size_t)pb_b * TT + t) * HH + pb_j;
            yb[yi] = hb;
            ys[yi] = hs;
        }

        // ---- signal own group's h for step t+1 ----
        __syncthreads();
        if (tid == 0) {
            __threadfence();                   // release h writes
            atomicAdd((unsigned*)&g_cnt2[ks * 8], 1u);
        }
    }
}

// ---------------- launch ----------------
extern "C" void kernel_launch(void* const* d_in, const int* in_sizes, int n_in,
                              void* d_out, int out_size)
{
    const int*   x    = (const int*)  d_in[0];
    const float* emb  = (const float*)d_in[1];
    const float* Wih0 = (const float*)d_in[2];
    const float* Whh0 = (const float*)d_in[3];
    const float* b0   = (const float*)d_in[4];
    const float* Wih1 = (const float*)d_in[5];
    const float* Whh1 = (const float*)d_in[6];
    const float* b1   = (const float*)d_in[7];
    const float* fcW  = (const float*)d_in[8];
    const float* fcb  = (const float*)d_in[9];
    const float* h0   = (const float*)d_in[10];
    const float* c0   = (const float*)d_in[11];
    float* out = (float*)d_out;

    float *gx;
    __nv_bfloat16 *y0b, *y0s, *y1b, *y1s, *wAb, *wAs, *embb, *embs;
    cudaGetSymbolAddress((void**)&gx,   g_gx);
    cudaGetSymbolAddress((void**)&y0b,  g_y0b);
    cudaGetSymbolAddress((void**)&y0s,  g_y0s);
    cudaGetSymbolAddress((void**)&y1b,  g_y1b);
    cudaGetSymbolAddress((void**)&y1s,  g_y1s);
    cudaGetSymbolAddress((void**)&wAb,  g_wAb);
    cudaGetSymbolAddress((void**)&wAs,  g_wAs);
    cudaGetSymbolAddress((void**)&embb, g_embb);
    cudaGetSymbolAddress((void**)&embs, g_embs);

    const int LSTM_SMEM = (2 * 64 * 256 + 2 * 64 * 64) * (int)sizeof(uint32_t);  // 160 KB
    cudaFuncSetAttribute(lstm_layer, cudaFuncAttributeMaxDynamicSharedMemorySize, LSTM_SMEM);

    const int SG_SMEM = 65536 + 128;
    cudaFuncSetAttribute(sgemm_ldsm<true,  true>,  cudaFuncAttributeMaxDynamicSharedMemorySize, SG_SMEM);
    cudaFuncSetAttribute(sgemm_ldsm<false, true>,  cudaFuncAttributeMaxDynamicSharedMemorySize, SG_SMEM);
    cudaFuncSetAttribute(sgemm_ldsm<false, false>, cudaFuncAttributeMaxDynamicSharedMemorySize, SG_SMEM);

    const int M = BB * TT;  // 16384

    cvt_split_kernel<<<512, 256>>>(emb, embb, embs, VV * HH);
    cvt_split_kernel<<<4096, 256>>>(Wih0, wAb, wAs, NG * HH);

    sgemm_ldsm<true, true><<<dim3(NG / 128, M / 128), 256, SG_SMEM>>>(
        embb, embs, x, wAb, wAs, b0, gx, M, NG, HH);
    lstm_layer<<<128, 512, LSTM_SMEM>>>(gx, Whh0, h0, c0, y0b, y0s);

    cvt_split_kernel<<<4096, 256>>>(Wih1, wAb, wAs, NG * HH);

    sgemm_ldsm<false, true><<<dim3(NG / 128, M / 128), 256, SG_SMEM>>>(
        y0b, y0s, nullptr, wAb, wAs, b1, gx, M, NG, HH);
    lstm_layer<<<128, 512, LSTM_SMEM>>>(gx, Whh1, h0 + BB * HH, c0 + BB * HH, y1b, y1s);

    cvt_split_kernel<<<1024, 256>>>(fcW, wAb, wAs, VV * HH);
    sgemm_ldsm<false, false><<<dim3(VV / 128, M / 128), 256, SG_SMEM>>>(
        y1b, y1s, nullptr, wAb, wAs, fcb, out, M, VV, HH);
}

// round 17
// speedup vs baseline: 1.1510x; 1.1510x over previous
#include <cuda_runtime.h>
#include <cuda_bf16.h>
#include <math.h>
#include <stdint.h>

#define BB 64
#define TT 256
#define HH 1024
#define VV 128
#define NG 4096   // 4*H

// ---------------- device scratch (no allocations allowed) ----------------
__device__ float g_gx[BB * TT * NG];              // gate pre-activations, T-major [T][B][4H]
__device__ __nv_bfloat16 g_y0b[BB * TT * HH];     // layer-0 output big
__device__ __nv_bfloat16 g_y0s[BB * TT * HH];     // layer-0 output small
__device__ __nv_bfloat16 g_y1b[BB * TT * HH];     // layer-1 output big
__device__ __nv_bfloat16 g_y1s[BB * TT * HH];     // layer-1 output small
__device__ float g_hbuf[2][BB * HH];              // hidden state double buffer (fp32)
__device__ float g_c[BB * HH];                    // cell state (CTA-private cells)
__device__ float g_part[2][8 * BB * NG];          // k-split partials, double-buffered
__device__ __nv_bfloat16 g_wAb[NG * HH];          // W_ih / fc_W big
__device__ __nv_bfloat16 g_wAs[NG * HH];          // W_ih / fc_W small
__device__ __nv_bfloat16 g_embb[VV * HH];         // embedding big
__device__ __nv_bfloat16 g_embs[VV * HH];         // embedding small
__device__ unsigned g_barc;                       // global barrier arrival counter (init only)
__device__ volatile unsigned g_barsf[16 * 8];     // 16 release flags, 32B-spaced
__device__ volatile unsigned g_cnt2[8 * 8];       // per-ks-group h-ready counters (monotonic)
__device__ volatile unsigned g_cntcs[16 * 8];     // per-col-tile partials-ready counters (monotonic)

// ---------------- helpers ----------------
__device__ __forceinline__ void bf16_split(float x, __nv_bfloat16& b, __nv_bfloat16& s) {
    b = __float2bfloat16(x);
    s = __float2bfloat16(x - __bfloat162float(b));
}

__device__ __forceinline__ uint32_t pack_bf2(__nv_bfloat16 lo, __nv_bfloat16 hi) {
    __nv_bfloat162 t = __halves2bfloat162(lo, hi);
    return *reinterpret_cast<uint32_t*>(&t);
}

__device__ __forceinline__ int swz(int k2) {     // lstm custom swizzle (k2 mod 8)
    return 8 * (k2 & 3) + 16 * ((k2 >> 2) & 1);
}

__device__ __forceinline__ uint32_t sw64(uint32_t x) {   // SW64 (sgemm)
    return x ^ ((x >> 3) & 0x30);
}

__device__ __forceinline__ uint32_t smem_u32(const void* p) {
    uint32_t a;
    asm("{ .reg .u64 t; cvta.to.shared.u64 t, %1; cvt.u32.u64 %0, t; }" : "=r"(a) : "l"(p));
    return a;
}

__device__ __forceinline__ void mma_bf16(float* d, const uint32_t* a, const uint32_t* b) {
    asm volatile(
        "mma.sync.aligned.m16n8k16.row.col.f32.bf16.bf16.f32 "
        "{%0,%1,%2,%3}, {%4,%5,%6,%7}, {%8,%9}, {%0,%1,%2,%3};\n"
        : "+f"(d[0]), "+f"(d[1]), "+f"(d[2]), "+f"(d[3])
        : "r"(a[0]), "r"(a[1]), "r"(a[2]), "r"(a[3]), "r"(b[0]), "r"(b[1]));
}

__device__ __forceinline__ void ldsm4(uint32_t* r, uint32_t addr) {
    asm volatile(
        "ldmatrix.sync.aligned.m8n8.x4.shared.b16 {%0,%1,%2,%3}, [%4];"
        : "=r"(r[0]), "=r"(r[1]), "=r"(r[2]), "=r"(r[3]) : "r"(addr));
}

#define CP_ASYNC16(dst, src) \
    asm volatile("cp.async.cg.shared.global [%0], [%1], 16;" :: "r"(dst), "l"(src))
#define CP_COMMIT() asm volatile("cp.async.commit_group;" ::: "memory")
#define CP_WAIT1()  asm volatile("cp.async.wait_group 1;" ::: "memory")
#define CP_WAIT0()  asm volatile("cp.async.wait_group 0;" ::: "memory")

__device__ __forceinline__ float rcp_approx(float d) {
    float r;
    asm("rcp.approx.f32 %0, %1;" : "=f"(r) : "f"(d));
    return r;
}

__device__ __forceinline__ float fast_sigmoid(float x) {   // 1/(1+e^-x)
    const float a = fmaxf(fminf(-x, 40.f), -40.f);
    return rcp_approx(1.f + __expf(a));
}

__device__ __forceinline__ float fast_tanh(float x) {      // 1 - 2/(e^{2x}+1)
    const float a = fmaxf(fminf(2.f * x, 40.f), -40.f);
    return 1.f - 2.f * rcp_approx(__expf(a) + 1.f);
}

// Fused 3-product 16-k chunk for the lstm (k-major custom-swizzled layout; R13-proven)
template<int LDA>
__device__ __forceinline__ void mma_chunk3(const uint32_t* Ab32, const uint32_t* As32,
                                           const uint32_t* Bb32, const uint32_t* Bs32,
                                           int ldb, int k2b,
                                           float acc[4][4][4],
                                           int mbase, int nbase, int r, int q)
{
    const int s0 = 8 * r;
    const int s1 = 8 * r + 16;
    const int ra0 = (k2b + r) * LDA;
    const int ra1 = (k2b + r + 4) * LDA;
    const int rb0 = (k2b + r) * ldb;
    const int rb1 = (k2b + r + 4) * ldb;
    uint32_t bb[4][2], bs[4][2];
    #pragma unroll
    for (int nf = 0; nf < 4; nf++) {
        const int cb = nbase + nf * 8 + q;
        bb[nf][0] = Bb32[rb0 + (cb ^ s0)];
        bb[nf][1] = Bb32[rb1 + (cb ^ s1)];
        bs[nf][0] = Bs32[rb0 + (cb ^ s0)];
        bs[nf][1] = Bs32[rb1 + (cb ^ s1)];
    }
    {
        uint32_t ab[4][4];
        #pragma unroll
        for (int mf = 0; mf < 4; mf++) {
            const int c0 = mbase + mf * 16 + q;
            ab[mf][0] = Ab32[ra0 + (c0 ^ s0)];
            ab[mf][1] = Ab32[ra0 + ((c0 + 8) ^ s0)];
            ab[mf][2] = Ab32[ra1 + (c0 ^ s1)];
            ab[mf][3] = Ab32[ra1 + ((c0 + 8) ^ s1)];
        }
        #pragma unroll
        for (int mf = 0; mf < 4; mf++)
            #pragma unroll
            for (int nf = 0; nf < 4; nf++)
                mma_bf16(acc[mf][nf], ab[mf], bb[nf]);
        #pragma unroll
        for (int mf = 0; mf < 4; mf++)
            #pragma unroll
            for (int nf = 0; nf < 4; nf++)
                mma_bf16(acc[mf][nf], ab[mf], bs[nf]);
    }
    {
        uint32_t as[4][4];
        #pragma unroll
        for (int mf = 0; mf < 4; mf++) {
            const int c0 = mbase + mf * 16 + q;
            as[mf][0] = As32[ra0 + (c0 ^ s0)];
            as[mf][1] = As32[ra0 + ((c0 + 8) ^ s0)];
            as[mf][2] = As32[ra1 + (c0 ^ s1)];
            as[mf][3] = As32[ra1 + ((c0 + 8) ^ s1)];
        }
        #pragma unroll
        for (int mf = 0; mf < 4; mf++)
            #pragma unroll
            for (int nf = 0; nf < 4; nf++)
                mma_bf16(acc[mf][nf], as[mf], bb[nf]);
    }
}

// ---------------- global barrier (init only) ----------------
__device__ __forceinline__ void grid_bar(unsigned* sense) {
    __syncthreads();
    if (threadIdx.x == 0) {
        unsigned s = *sense ^ 1u;
        *sense = s;
        __threadfence();                       // release
        unsigned prev = atomicAdd(&g_barc, 1u);
        if (prev == gridDim.x - 1) {
            g_barc = 0u;
            __threadfence();
            #pragma unroll
            for (int i = 0; i < 16; i++) g_barsf[i * 8] = s;
        } else {
            volatile unsigned* f = &g_barsf[(blockIdx.x >> 3) * 8];
            while (*f != s) { }
            __threadfence();                   // acquire
        }
    }
    __syncthreads();
}

// ---------------- fp32 -> (bf16 big, bf16 small) split ----------------
__global__ void cvt_split_kernel(const float* __restrict__ src,
                                 __nv_bfloat16* __restrict__ dstb,
                                 __nv_bfloat16* __restrict__ dsts, int n) {
    for (int i = blockIdx.x * blockDim.x + threadIdx.x; i < n; i += gridDim.x * blockDim.x) {
        __nv_bfloat16 b, s;
        bf16_split(src[i], b, s);
        dstb[i] = b;
        dsts[i] = s;
    }
}

// ---------------- ldmatrix split-bf16 SGEMM, 3-stage cp.async pipeline ----------------
// BM=128, BN=128, BK=32 slices, 3-stage circular smem (96 KB), 8 warps (2m x 4n).
// Smem per stage: [Ab 8K | As 8K | Bb 8K | Bs 8K], m/n-major 64-B rows, SW64.
template <bool GATHER, bool TMAJOR>
__global__ __launch_bounds__(256, 2)
void sgemm_ldsm(const __nv_bfloat16* __restrict__ Ab, const __nv_bfloat16* __restrict__ As_,
                const int* __restrict__ tok,
                const __nv_bfloat16* __restrict__ Wb, const __nv_bfloat16* __restrict__ Ws_,
                const float* __restrict__ bias,
                float* __restrict__ C, int M, int N, int K)
{
    extern __shared__ uint8_t smg_raw[];
    uint8_t* smg = (uint8_t*)(((uintptr_t)smg_raw + 127) & ~(uintptr_t)127);
    const uint32_t smb = smem_u32(smg);

    const int tid = threadIdx.x;
    const int warp = tid >> 5;
    const int lane = tid & 31;
    const int m0 = blockIdx.y * 128;
    const int n0 = blockIdx.x * 128;
    const int mbase = (warp >> 2) * 64;
    const int nbase = (warp & 3) * 32;
    const int r = lane & 3;
    const int q = lane >> 2;

    uint32_t offA[4], offB[2];
    {
        const int ar = (lane & 7) + 8 * ((lane >> 3) & 1);
        const int abyt = ((lane >> 4) & 1) * 16;
        #pragma unroll
        for (int mf = 0; mf < 4; mf++)
            offA[mf] = sw64((mbase + mf * 16 + ar) * 64 + abyt);
        const int br = (lane & 7) + 8 * ((lane >> 4) & 1);
        const int bbyt = ((lane >> 3) & 1) * 16;
        #pragma unroll
        for (int n2 = 0; n2 < 2; n2++)
            offB[n2] = sw64((nbase + n2 * 16 + br) * 64 + bbyt);
    }

    // staging offsets: row = tid>>1, 32-B half = tid&1 (two 16-B cp.async each)
    const int srow = tid >> 1;
    const int so0i = srow * 64 + (tid & 1) * 32;
    const uint32_t so0 = sw64(so0i);
    const uint32_t so1 = sw64(so0i + 16);

    size_t aoff;
    if (GATHER) aoff = (size_t)tok[m0 + srow] * K;
    else        aoff = (size_t)(m0 + srow) * K;
    const __nv_bfloat16* arb = Ab  + aoff + (tid & 1) * 16;
    const __nv_bfloat16* ars = As_ + aoff + (tid & 1) * 16;
    const __nv_bfloat16* wrb = Wb  + (size_t)(n0 + srow) * K + (tid & 1) * 16;
    const __nv_bfloat16* wrs = Ws_ + (size_t)(n0 + srow) * K + (tid & 1) * 16;

    float acc[4][4][4];
    #pragma unroll
    for (int mf = 0; mf < 4; mf++)
        #pragma unroll
        for (int nf = 0; nf < 4; nf++)
            #pragma unroll
            for (int i = 0; i < 4; i++) acc[mf][nf][i] = 0.f;

    const int nslice = K / 32;

    // issue one slice's copies into stage buffer (8 x 16-B cp.async + commit)
    auto issue = [&](int s) {
        const uint32_t bo = smb + (uint32_t)(s % 3) * 32768u;
        const int k0 = s * 32;
        CP_ASYNC16(bo + so0,          arb + k0);
        CP_ASYNC16(bo + so1,          arb + k0 + 8);
        CP_ASYNC16(bo + 8192 + so0,   ars + k0);
        CP_ASYNC16(bo + 8192 + so1,   ars + k0 + 8);
        CP_ASYNC16(bo + 16384 + so0,  wrb + k0);
        CP_ASYNC16(bo + 16384 + so1,  wrb + k0 + 8);
        CP_ASYNC16(bo + 24576 + so0,  wrs + k0);
        CP_ASYNC16(bo + 24576 + so1,  wrs + k0 + 8);
        CP_COMMIT();
    };

    issue(0);
    issue(1);

    for (int s = 0; s < nslice; s++) {
        if (s + 1 < nslice) CP_WAIT1();
        else                CP_WAIT0();
        __syncthreads();
        if (s + 2 < nslice) issue(s + 2);

        const uint32_t bAb = smb + (uint32_t)(s % 3) * 32768u;
        const uint32_t bAs = bAb + 8192;
        const uint32_t bBb = bAb + 16384;
        const uint32_t bBs = bAb + 24576;
        #pragma unroll
        for (int kc = 0; kc < 2; kc++) {
            const uint32_t kcb = (uint32_t)kc * 32u;
            uint32_t abf[4][4], bbf[2][4];
            #pragma unroll
            for (int mf = 0; mf < 4; mf++) ldsm4(abf[mf], bAb + (offA[mf] ^ kcb));
            #pragma unroll
            for (int n2 = 0; n2 < 2; n2++) ldsm4(bbf[n2], bBb + (offB[n2] ^ kcb));
            #pragma unroll
            for (int mf = 0; mf < 4; mf++)
                #pragma unroll
                for (int nf = 0; nf < 4; nf++)
                    mma_bf16(acc[mf][nf], abf[mf], &bbf[nf >> 1][(nf & 1) * 2]);
            {
                uint32_t bsf[2][4];
                #pragma unroll
                for (int n2 = 0; n2 < 2; n2++) ldsm4(bsf[n2], bBs + (offB[n2] ^ kcb));
                #pragma unroll
                for (int mf = 0; mf < 4; mf++)
                    #pragma unroll
                    for (int nf = 0; nf < 4; nf++)
                        mma_bf16(acc[mf][nf], abf[mf], &bsf[nf >> 1][(nf & 1) * 2]);
            }
            {
                uint32_t asf[4][4];
                #pragma unroll
                for (int mf = 0; mf < 4; mf++) ldsm4(asf[mf], bAs + (offA[mf] ^ kcb));
                #pragma unroll
                for (int mf = 0; mf < 4; mf++)
                    #pragma unroll
                    for (int nf = 0; nf < 4; nf++)
                        mma_bf16(acc[mf][nf], asf[mf], &bbf[nf >> 1][(nf & 1) * 2]);
            }
        }
        __syncthreads();
    }

    #pragma unroll
    for (int nf = 0; nf < 4; nf++) {
        const int n = n0 + nbase + nf * 8 + 2 * r;
        const float b0v = bias[n];
        const float b1v = bias[n + 1];
        #pragma unroll
        for (int mf = 0; mf < 4; mf++) {
            const int m = m0 + mbase + mf * 16 + q;
            size_t row0, row1;
            if (TMAJOR) {
                row0 = (size_t)((m % TT) * BB + m / TT);
                const int m8 = m + 8;
                row1 = (size_t)((m8 % TT) * BB + m8 / TT);
            } else {
                row0 = (size_t)m;
                row1 = (size_t)(m + 8);
            }
            float2 o0 = {acc[mf][nf][0] + b0v, acc[mf][nf][1] + b1v};
            float2 o1 = {acc[mf][nf][2] + b0v, acc[mf][nf][3] + b1v};
            *(float2*)(C + row0 * N + n) = o0;
            *(float2*)(C + row1 * N + n) = o1;
        }
    }
}

// ---------------- persistent LSTM layer kernel (R13, byte-identical) ----------------
// grid = 128 CTAs (16 col tiles x 8 k-splits), 256 threads. W stationary in smem.
// Per step: h-ready via cnt2[ks] (16 producers), partials-ready via 4 of 16
// per-col-tile counters (8 producers each). No global rendezvous after init.
__global__ __launch_bounds__(256, 1)
void lstm_layer(const float* __restrict__ gx, const float* __restrict__ Whh,
                const float* __restrict__ h0, const float* __restrict__ c0,
                __nv_bfloat16* __restrict__ yb, __nv_bfloat16* __restrict__ ys)
{
    extern __shared__ uint32_t dynsm[];
    uint32_t* Wb_sm = dynsm;              // [64 k2][256]
    uint32_t* Ws_sm = dynsm + 64 * 256;
    __shared__ uint32_t hsb[64 * 64];     // [64 k2][64 b]
    __shared__ uint32_t hss[64 * 64];

    const int tid = threadIdx.x;
    const int bid = blockIdx.x;       // 0..127
    const int cs  = bid & 15;
    const int ks  = bid >> 4;
    const int col0 = cs * 256;
    const int gtid = bid * 256 + tid;

    const int warp = tid >> 5;
    const int lane = tid & 31;
    const int r = lane & 3;
    const int q = lane >> 2;
    const int nbase = warp * 32;

    unsigned sense = g_barsf[(bid >> 3) * 8];

    // ---- one-time W slice load + split ----
    {
        const float* wsrc = Whh + (size_t)(col0 + tid) * HH + ks * 128;
        #pragma unroll
        for (int g = 0; g < 16; g++) {
            float4 v0 = *(const float4*)(wsrc + 8 * g);
            float4 v1 = *(const float4*)(wsrc + 8 * g + 4);
            const float wv[8] = {v0.x, v0.y, v0.z, v0.w, v1.x, v1.y, v1.z, v1.w};
            #pragma unroll
            for (int j = 0; j < 4; j++) {
                __nv_bfloat16 b0, s0, b1, s1;
                bf16_split(wv[2 * j], b0, s0);
                bf16_split(wv[2 * j + 1], b1, s1);
                const int k2 = 4 * g + j;
                const int idx = k2 * 256 + (tid ^ swz(k2));
                Wb_sm[idx] = pack_bf2(b0, b1);
                Ws_sm[idx] = pack_bf2(s0, s1);
            }
        }
    }

    // init state + reset monotonic counters
    for (int i = gtid; i < BB * HH; i += 128 * 256) {
        g_hbuf[0][i] = h0[i];
        g_c[i] = c0[i];
    }
    if (tid == 0 && bid < 8)  *((volatile unsigned*)&g_cnt2[bid * 8])  = 0u;
    if (tid == 0 && bid < 16) *((volatile unsigned*)&g_cntcs[bid * 8]) = 0u;
    grid_bar(&sense);

    const int hrow = tid >> 2;              // b 0..63
    const int hq   = (tid & 3) * 4;         // k offset within 16-chunk
    const int hk2  = hq >> 1;               // local k2 offset {0,2,4,6}

    // phase-B ks-local ownership: b in [4cs,4cs+4), j in [128ks,128ks+128)
    const int pb_b  = 4 * cs + (tid >> 6);
    const int pb_j  = 128 * ks + (tid & 63) * 2;
    const int cellp = pb_b * 1024 + pb_j;
    const int src_tile0 = ks >> 1;          // partials source col tiles: src_tile0 + 4*g

    for (int t = 0; t < TT; t++) {
        const int par = t & 1;
        float* partp = g_part[par];

        // ---- group wait: own ks-group's h values for this step are ready ----
        if (t > 0) {
            if (tid == 0) {
                const unsigned need = 16u * (unsigned)t;
                volatile unsigned* cp = &g_cnt2[ks * 8];
                while (*cp < need) { }
                __threadfence();               // acquire
            }
            __syncthreads();
        }

        // ---- stage h slice (64 b x 128 k) from hbuf[par], split, one sync ----
        const float* hbase = g_hbuf[par] + (size_t)hrow * HH + ks * 128;
        #pragma unroll
        for (int g8 = 0; g8 < 8; g8++) {
            float4 hv = *(const float4*)(hbase + g8 * 16 + hq);
            __nv_bfloat16 b0, s0v, b1, s1v, b2, s2v, b3, s3v;
            bf16_split(hv.x, b0, s0v);
            bf16_split(hv.y, b1, s1v);
            bf16_split(hv.z, b2, s2v);
            bf16_split(hv.w, b3, s3v);
            const int k2a = g8 * 8 + hk2;
            const int i0 = k2a * 64 + (hrow ^ swz(k2a));
            const int i1 = (k2a + 1) * 64 + (hrow ^ swz(k2a + 1));
            hsb[i0] = pack_bf2(b0, b1);
            hss[i0] = pack_bf2(s0v, s1v);
            hsb[i1] = pack_bf2(b2, b3);
            hss[i1] = pack_bf2(s2v, s3v);
        }
        __syncthreads();

        float acc[4][4][4];
        #pragma unroll
        for (int mf = 0; mf < 4; mf++)
            #pragma unroll
            for (int nf = 0; nf < 4; nf++)
                #pragma unroll
                for (int i = 0; i < 4; i++) acc[mf][nf][i] = 0.f;

        #pragma unroll
        for (int kc = 0; kc < 8; kc++)
            mma_chunk3<64>(hsb, hss, Wb_sm, Ws_sm, 256, kc * 8,
                           acc, 0, nbase, r, q);

        // write partials P[par][ks][b][col]
        #pragma unroll
        for (int nf = 0; nf < 4; nf++) {
            const int col = col0 + nbase + nf * 8 + 2 * r;
            #pragma unroll
            for (int mf = 0; mf < 4; mf++) {
                const int b = mf * 16 + q;
                float2 o0 = {acc[mf][nf][0], acc[mf][nf][1]};
                float2 o1 = {acc[mf][nf][2], acc[mf][nf][3]};
                *(float2*)(&partp[((size_t)ks * BB + b) * NG + col])     = o0;
                *(float2*)(&partp[((size_t)ks * BB + b + 8) * NG + col]) = o1;
            }
        }

        // ---- prefetch gx[t] and c (CTA-private cells; program-order safe) ----
        const float* gr = gx + (size_t)t * BB * NG + (size_t)pb_b * NG + pb_j;
        const float2 xg0 = *(const float2*)(gr);
        const float2 xg1 = *(const float2*)(gr + 1024);
        const float2 xg2 = *(const float2*)(gr + 2048);
        const float2 xg3 = *(const float2*)(gr + 3072);
        float2 cv = *(const float2*)(&g_c[cellp]);

        // ---- signal own partials for step t (per-col-tile counter) ----
        __syncthreads();
        if (tid == 0) {
            __threadfence();                   // release partial writes
            atomicAdd((unsigned*)&g_cntcs[cs * 8], 1u);
        }

        // ---- wait: the 4 source col tiles' partials (all 8 k-splits) ready ----
        if (tid < 4) {
            const unsigned need = 8u * (unsigned)(t + 1);
            volatile unsigned* cp = &g_cntcs[(src_tile0 + 4 * tid) * 8];
            while (*cp < need) { }
            __threadfence();                   // acquire
        }
        __syncthreads();

        // ---- Phase B: own cells, read partials[par], write hbuf[par^1] ----
        {
            float2 gi = xg0, gf = xg1, gg = xg2, go = xg3;
            #pragma unroll
            for (int s = 0; s < 8; s++) {
                const float* pp = &partp[((size_t)s * BB + pb_b) * NG + pb_j];
                const float2 p0 = *(const float2*)(pp);
                const float2 p1 = *(const float2*)(pp + 1024);
                const float2 p2 = *(const float2*)(pp + 2048);
                const float2 p3 = *(const float2*)(pp + 3072);
                gi.x += p0.x; gi.y += p0.y;
                gf.x += p1.x; gf.y += p1.y;
                gg.x += p2.x; gg.y += p2.y;
                go.x += p3.x; go.y += p3.y;
            }

            const float si0 = fast_sigmoid(gi.x);
            const float si1 = fast_sigmoid(gi.y);
            const float sf0 = fast_sigmoid(gf.x);
            const float sf1 = fast_sigmoid(gf.y);
            const float so0 = fast_sigmoid(go.x);
            const float so1 = fast_sigmoid(go.y);
            cv.x = sf0 * cv.x + si0 * fast_tanh(gg.x);
            cv.y = sf1 * cv.y + si1 * fast_tanh(gg.y);
            const float hv0 = so0 * fast_tanh(cv.x);
            const float hv1 = so1 * fast_tanh(cv.y);
            *(float2*)(&g_c[cellp]) = cv;
            float2 hw = {hv0, hv1};
            *(float2*)(&g_hbuf[par ^ 1][cellp]) = hw;

            __nv_bfloat16 hb0, hs0, hb1, hs1;
            bf16_split(hv0, hb0, hs0);
            bf16_split(hv1, hb1, hs1);
            const size_t yi = ((size_t)pb_b * TT + t) * HH + pb_j;
            *(uint32_t*)(yb + yi) = pack_bf2(hb0, hb1);
            *(uint32_t*)(ys + yi) = pack_bf2(hs0, hs1);
        }

        // ---- signal own group's h contribution for step t+1 ----
        __syncthreads();
        if (tid == 0) {
            __threadfence();                   // release h writes
            atomicAdd((unsigned*)&g_cnt2[ks * 8], 1u);
        }
    }
}

// ---------------- launch ----------------
extern "C" void kernel_launch(void* const* d_in, const int* in_sizes, int n_in,
                              void* d_out, int out_size)
{
    const int*   x    = (const int*)  d_in[0];
    const float* emb  = (const float*)d_in[1];
    const float* Wih0 = (const float*)d_in[2];
    const float* Whh0 = (const float*)d_in[3];
    const float* b0   = (const float*)d_in[4];
    const float* Wih1 = (const float*)d_in[5];
    const float* Whh1 = (const float*)d_in[6];
    const float* b1   = (const float*)d_in[7];
    const float* fcW  = (const float*)d_in[8];
    const float* fcb  = (const float*)d_in[9];
    const float* h0   = (const float*)d_in[10];
    const float* c0   = (const float*)d_in[11];
    float* out = (float*)d_out;

    float *gx;
    __nv_bfloat16 *y0b, *y0s, *y1b, *y1s, *wAb, *wAs, *embb, *embs;
    cudaGetSymbolAddress((void**)&gx,   g_gx);
    cudaGetSymbolAddress((void**)&y0b,  g_y0b);
    cudaGetSymbolAddress((void**)&y0s,  g_y0s);
    cudaGetSymbolAddress((void**)&y1b,  g_y1b);
    cudaGetSymbolAddress((void**)&y1s,  g_y1s);
    cudaGetSymbolAddress((void**)&wAb,  g_wAb);
    cudaGetSymbolAddress((void**)&wAs,  g_wAs);
    cudaGetSymbolAddress((void**)&embb, g_embb);
    cudaGetSymbolAddress((void**)&embs, g_embs);

    const int LSTM_SMEM = 64 * 256 * 2 * (int)sizeof(uint32_t);  // 128 KB dynamic
    cudaFuncSetAttribute(lstm_layer, cudaFuncAttributeMaxDynamicSharedMemorySize, LSTM_SMEM);

    const int SG_SMEM = 3 * 32768 + 128;   // 3-stage pipeline
    cudaFuncSetAttribute(sgemm_ldsm<true,  true>,  cudaFuncAttributeMaxDynamicSharedMemorySize, SG_SMEM);
    cudaFuncSetAttribute(sgemm_ldsm<false, true>,  cudaFuncAttributeMaxDynamicSharedMemorySize, SG_SMEM);
    cudaFuncSetAttribute(sgemm_ldsm<false, false>, cudaFuncAttributeMaxDynamicSharedMemorySize, SG_SMEM);

    const int M = BB * TT;  // 16384

    cvt_split_kernel<<<512, 256>>>(emb, embb, embs, VV * HH);
    cvt_split_kernel<<<4096, 256>>>(Wih0, wAb, wAs, NG * HH);

    sgemm_ldsm<true, true><<<dim3(NG / 128, M / 128), 256, SG_SMEM>>>(
        embb, embs, x, wAb, wAs, b0, gx, M, NG, HH);
    lstm_layer<<<128, 256, LSTM_SMEM>>>(gx, Whh0, h0, c0, y0b, y0s);

    cvt_split_kernel<<<4096, 256>>>(Wih1, wAb, wAs, NG * HH);

    sgemm_ldsm<false, true><<<dim3(NG / 128, M / 128), 256, SG_SMEM>>>(
        y0b, y0s, nullptr, wAb, wAs, b1, gx, M, NG, HH);
    lstm_layer<<<128, 256, LSTM_SMEM>>>(gx, Whh1, h0 + BB * HH, c0 + BB * HH, y1b, y1s);

    cvt_split_kernel<<<1024, 256>>>(fcW, wAb, wAs, VV * HH);
    sgemm_ldsm<false, false><<<dim3(VV / 128, M / 128), 256, SG_SMEM>>>(
        y1b, y1s, nullptr, wAb, wAs, fcb, out, M, VV, HH);
}